// round 1
// baseline (speedup 1.0000x reference)
#include <cuda_runtime.h>
#include <math.h>

#define BB 64
#define DD 4096
#define HH 32
#define HKV 8
#define GG 4
#define DHD 128
#define WW 2048

// ---------------- device scratch (no allocations allowed) ----------------
__device__ float g_part[4 * 64 * 6144];   // split-K partials (max N=6144)
__device__ float g_q[64 * 4096];          // rope'd + pre-scaled q
__device__ float g_k[64 * 1024];          // rope'd new k
__device__ float g_v[64 * 1024];          // new v
__device__ float g_attn[64 * 4096];       // attention output
__device__ float g_o[64 * 4096];          // after W_o

// ---------------- f32x2 packed helpers ----------------
__device__ __forceinline__ unsigned long long pack2(float x) {
    unsigned long long r;
    asm("mov.b64 %0, {%1, %1};" : "=l"(r) : "r"(__float_as_uint(x)));
    return r;
}
__device__ __forceinline__ void ffma2(unsigned long long& d, unsigned long long a,
                                      unsigned long long b) {
    asm("fma.rn.f32x2 %0, %1, %2, %0;" : "+l"(d) : "l"(a), "l"(b));
}

// ---------------- GEMM: part[s][64][N] += A[64,Kslice] @ W[Ntile,Kslice]^T --------
// amode: 0 = A1 (x), 1 = g_attn, 2 = concat(x | g_o) with switch at k=4096
// Block: 256 threads, tile M=64 x N=128, Kc=16. Thread microtile 8 rows x 4 cols.
__global__ __launch_bounds__(256) void gemm_part(
    const float* __restrict__ A1,
    const float* __restrict__ W0, const float* __restrict__ W1,
    const float* __restrict__ W2, int nb1, int nb2, int K, int partN, int amode) {
    __shared__ float xs[16 * 64];
    __shared__ float ws[16 * 128];

    const int tid = threadIdx.x;
    const int tx = tid & 31;
    const int ty = tid >> 5;
    const int n0 = blockIdx.x * 128;

    const float* Wb;
    int nrel;
    if (n0 < nb1)      { Wb = W0; nrel = n0; }
    else if (n0 < nb2) { Wb = W1; nrel = n0 - nb1; }
    else               { Wb = W2; nrel = n0 - nb2; }

    const int S = gridDim.y;
    const int Ks = K / S;
    const int kt0 = blockIdx.y * Ks;

    unsigned long long acc0[8], acc1[8];
#pragma unroll
    for (int r = 0; r < 8; r++) { acc0[r] = 0ULL; acc1[r] = 0ULL; }

    // loader indices
    const int am = tid >> 2;        // 0..63  (row)
    const int ak = (tid & 3) * 4;   // 0,4,8,12
    const int wn = tid >> 1;        // 0..127 (weight row within tile)
    const int wk = (tid & 1) * 8;   // 0 or 8

    for (int kt = kt0; kt < kt0 + Ks; kt += 16) {
        // ---- load A tile [64 x 16] (transposed into k-major) ----
        {
            const int kg = kt + ak;
            const float* Ar;
            if (amode == 0)      Ar = A1 + am * 4096 + kg;
            else if (amode == 1) Ar = g_attn + am * 4096 + kg;
            else                 Ar = (kg < 4096) ? (A1 + am * 4096 + kg)
                                                  : (g_o + am * 4096 + (kg - 4096));
            float4 av = *(const float4*)Ar;
            xs[(ak + 0) * 64 + am] = av.x;
            xs[(ak + 1) * 64 + am] = av.y;
            xs[(ak + 2) * 64 + am] = av.z;
            xs[(ak + 3) * 64 + am] = av.w;
        }
        // ---- load W tile [128 x 16] (transposed into k-major) ----
        {
            const float* Wrow = Wb + (size_t)(nrel + wn) * K + kt + wk;
            float4 w0 = *(const float4*)Wrow;
            float4 w1 = *(const float4*)(Wrow + 4);
            ws[(wk + 0) * 128 + wn] = w0.x;
            ws[(wk + 1) * 128 + wn] = w0.y;
            ws[(wk + 2) * 128 + wn] = w0.z;
            ws[(wk + 3) * 128 + wn] = w0.w;
            ws[(wk + 4) * 128 + wn] = w1.x;
            ws[(wk + 5) * 128 + wn] = w1.y;
            ws[(wk + 6) * 128 + wn] = w1.z;
            ws[(wk + 7) * 128 + wn] = w1.w;
        }
        __syncthreads();

        const unsigned long long* wsq = (const unsigned long long*)ws;
#pragma unroll
        for (int kk = 0; kk < 16; kk++) {
            const unsigned long long wA = wsq[kk * 64 + tx];
            const unsigned long long wB = wsq[kk * 64 + 32 + tx];
#pragma unroll
            for (int r = 0; r < 8; r++) {
                unsigned long long xx = pack2(xs[kk * 64 + ty * 8 + r]);
                ffma2(acc0[r], xx, wA);
                ffma2(acc1[r], xx, wB);
            }
        }
        __syncthreads();
    }

    // ---- write partials ----
    const int s = blockIdx.y;
#pragma unroll
    for (int r = 0; r < 8; r++) {
        const int row = ty * 8 + r;
        unsigned long long* p =
            (unsigned long long*)(g_part + (size_t)(s * 64 + row) * partN + n0);
        p[tx] = acc0[r];
        p[32 + tx] = acc1[r];
    }
}

// ---------------- pos (int32 / int64 / fp32 agnostic) ----------------
__device__ __forceinline__ float read_pos(const void* p) {
    int iv = *(const int*)p;
    if (iv >= 0 && iv < (1 << 26)) return (float)iv;
    return *(const float*)p;
}

// ---------------- reduce split-K partials of QKV + RoPE ----------------
// partN = 6144 : cols [0,4096) = q, [4096,5120) = k, [5120,6144) = v
__global__ __launch_bounds__(256) void reduce_rope_kernel(const void* posp) {
    const int p = blockIdx.x * 256 + threadIdx.x;  // pair index, 64*3072 total
    const int m = p / 3072;
    const int c = (p % 3072) * 2;

    float a0 = 0.f, a1 = 0.f;
#pragma unroll
    for (int s = 0; s < 4; s++) {
        const size_t base = (size_t)(s * 64 + m) * 6144 + c;
        a0 += g_part[base];
        a1 += g_part[base + 1];
    }

    if (c < 5120) {
        const float pos = read_pos(posp);
        const float ex = (float)(c & 127) * (1.0f / 128.0f);
        const float inv = powf(10000.0f, -ex);
        const float ang = pos * inv;
        float sn, cs;
        sincosf(ang, &sn, &cs);
        const float r0 = a0 * cs - a1 * sn;
        const float r1 = a0 * sn + a1 * cs;
        if (c < 4096) {
            const float sc = 0.08838834764831845f;  // 1/sqrt(128), folded into q
            g_q[m * 4096 + c]     = r0 * sc;
            g_q[m * 4096 + c + 1] = r1 * sc;
        } else {
            g_k[m * 1024 + (c - 4096)]     = r0;
            g_k[m * 1024 + (c - 4096) + 1] = r1;
        }
    } else {
        g_v[m * 1024 + (c - 5120)]     = a0;
        g_v[m * 1024 + (c - 5120) + 1] = a1;
    }
}

// ---------------- attention: one block per (b, kv) ----------------
__global__ __launch_bounds__(256) void attn_kernel(const float* __restrict__ kcache,
                                                   const float* __restrict__ vcache) {
    __shared__ float sq[4 * 128];
    __shared__ float ss[4 * 2048];
    __shared__ float red[8];
    __shared__ float sginv[4];
    __shared__ float spv[4 * 128];

    const int tid = threadIdx.x;
    const int bk = blockIdx.x;       // b*8 + kv
    const int b = bk >> 3;
    const int kv = bk & 7;

    // load pre-scaled q for 4 groups
    for (int i = tid; i < 512; i += 256) sq[i] = g_q[b * 4096 + kv * 512 + i];
    __syncthreads();

    // ---- scores: warp per key ----
    const int wid = tid >> 5, lane = tid & 31;
    const float* kbase = kcache + (size_t)bk * (2048 * 128);
    const float4 q0 = *(const float4*)(sq + 0 * 128 + lane * 4);
    const float4 q1 = *(const float4*)(sq + 1 * 128 + lane * 4);
    const float4 q2 = *(const float4*)(sq + 2 * 128 + lane * 4);
    const float4 q3 = *(const float4*)(sq + 3 * 128 + lane * 4);

#pragma unroll 2
    for (int key = wid; key < 2048; key += 8) {
        float4 kk;
        if (key < 2047)
            kk = *(const float4*)(kbase + (size_t)(key + 1) * 128 + lane * 4);
        else
            kk = *(const float4*)(g_k + bk * 128 + lane * 4);
        float s0 = kk.x * q0.x + kk.y * q0.y + kk.z * q0.z + kk.w * q0.w;
        float s1 = kk.x * q1.x + kk.y * q1.y + kk.z * q1.z + kk.w * q1.w;
        float s2 = kk.x * q2.x + kk.y * q2.y + kk.z * q2.z + kk.w * q2.w;
        float s3 = kk.x * q3.x + kk.y * q3.y + kk.z * q3.z + kk.w * q3.w;
#pragma unroll
        for (int off = 16; off; off >>= 1) {
            s0 += __shfl_xor_sync(0xffffffffu, s0, off);
            s1 += __shfl_xor_sync(0xffffffffu, s1, off);
            s2 += __shfl_xor_sync(0xffffffffu, s2, off);
            s3 += __shfl_xor_sync(0xffffffffu, s3, off);
        }
        if (lane == 0) {
            ss[0 * 2048 + key] = s0;
            ss[1 * 2048 + key] = s1;
            ss[2 * 2048 + key] = s2;
            ss[3 * 2048 + key] = s3;
        }
    }
    __syncthreads();

    // ---- softmax: 64 threads (2 warps) per group ----
    const int gg = tid >> 6, t64 = tid & 63;
    float mx = -1e30f;
    for (int w = t64; w < 2048; w += 64) mx = fmaxf(mx, ss[gg * 2048 + w]);
#pragma unroll
    for (int off = 16; off; off >>= 1)
        mx = fmaxf(mx, __shfl_xor_sync(0xffffffffu, mx, off));
    if (lane == 0) red[wid] = mx;
    __syncthreads();
    mx = fmaxf(red[gg * 2], red[gg * 2 + 1]);

    float sm = 0.f;
    for (int w = t64; w < 2048; w += 64) {
        const float e = __expf(ss[gg * 2048 + w] - mx);
        ss[gg * 2048 + w] = e;
        sm += e;
    }
#pragma unroll
    for (int off = 16; off; off >>= 1) sm += __shfl_xor_sync(0xffffffffu, sm, off);
    __syncthreads();  // all reads of red (max phase) done
    if (lane == 0) red[wid] = sm;
    __syncthreads();
    if (tid < 4) sginv[tid] = 1.0f / (red[tid * 2] + red[tid * 2 + 1]);
    __syncthreads();

    // ---- PV: thread owns d, 2-way split over keys ----
    const int d = tid & 127, half = tid >> 7;
    const float* vbase = vcache + (size_t)bk * (2048 * 128);
    float a0 = 0.f, a1 = 0.f, a2 = 0.f, a3 = 0.f;
    const int wbeg = half * 1024;
#pragma unroll 4
    for (int w = wbeg; w < wbeg + 1024; w++) {
        const float v = (w < 2047) ? vbase[(size_t)(w + 1) * 128 + d]
                                   : g_v[bk * 128 + d];
        a0 += ss[0 * 2048 + w] * v;
        a1 += ss[1 * 2048 + w] * v;
        a2 += ss[2 * 2048 + w] * v;
        a3 += ss[3 * 2048 + w] * v;
    }
    if (half == 1) {
        spv[0 * 128 + d] = a0;
        spv[1 * 128 + d] = a1;
        spv[2 * 128 + d] = a2;
        spv[3 * 128 + d] = a3;
    }
    __syncthreads();
    if (half == 0) {
        float* ob = g_attn + b * 4096 + kv * 512;
        ob[0 * 128 + d] = (a0 + spv[0 * 128 + d]) * sginv[0];
        ob[1 * 128 + d] = (a1 + spv[1 * 128 + d]) * sginv[1];
        ob[2 * 128 + d] = (a2 + spv[2 * 128 + d]) * sginv[2];
        ob[3 * 128 + d] = (a3 + spv[3 * 128 + d]) * sginv[3];
    }
}

// ---------------- reduce split-K partials of W_o -> g_o ----------------
__global__ __launch_bounds__(256) void reduce_o_kernel() {
    const int i = blockIdx.x * 256 + threadIdx.x;  // 64*4096
    const int m = i >> 12, n = i & 4095;
    float z = 0.f;
#pragma unroll
    for (int s = 0; s < 4; s++) z += g_part[(size_t)(s * 64 + m) * 4096 + n];
    g_o[i] = z;
}

// ---------------- reduce gate partials + sigmoid + final combine ----------------
__global__ __launch_bounds__(256) void final_kernel(const float* __restrict__ x,
                                                    const float* __restrict__ gb,
                                                    float* __restrict__ out) {
    const int i = blockIdx.x * 256 + threadIdx.x;  // 64*4096
    const int m = i >> 12, n = i & 4095;
    float z = 0.f;
#pragma unroll
    for (int s = 0; s < 4; s++) z += g_part[(size_t)(s * 64 + m) * 4096 + n];
    z += gb[n];
    const float sig = 1.0f / (1.0f + __expf(-z));
    out[i] = x[i] + sig * g_o[i];
}

// ---------------- launch ----------------
extern "C" void kernel_launch(void* const* d_in, const int* in_sizes, int n_in,
                              void* d_out, int out_size) {
    const float* x  = (const float*)d_in[0];
    const float* kc = (const float*)d_in[1];
    const float* vc = (const float*)d_in[2];
    const float* Wq = (const float*)d_in[3];
    const float* Wk = (const float*)d_in[4];
    const float* Wv = (const float*)d_in[5];
    const float* Wo = (const float*)d_in[6];
    const float* gw = (const float*)d_in[7];
    const float* gb = (const float*)d_in[8];
    const void*  pp = d_in[9];
    float* out = (float*)d_out;

    const int BIG = 1 << 30;

    // 1. fused QKV projection (split-K x4, N = 6144)
    gemm_part<<<dim3(48, 4), 256>>>(x, Wq, Wk, Wv, 4096, 5120, 4096, 6144, 0);
    // 2. reduce + RoPE (+ fold 1/sqrt(dh) into q)
    reduce_rope_kernel<<<768, 256>>>(pp);
    // 3. attention over sliding-window cache
    attn_kernel<<<512, 256>>>(kc, vc);
    // 4. output projection (A = g_attn)
    gemm_part<<<dim3(32, 4), 256>>>(x, Wo, Wo, Wo, BIG, BIG, 4096, 4096, 1);
    reduce_o_kernel<<<1024, 256>>>();
    // 5. gate GEMM over concat(x, o), K = 8192
    gemm_part<<<dim3(32, 4), 256>>>(x, gw, gw, gw, BIG, BIG, 8192, 4096, 2);
    // 6. reduce + bias + sigmoid + residual combine
    final_kernel<<<1024, 256>>>(x, gb, out);
}

// round 3
// speedup vs baseline: 1.1858x; 1.1858x over previous
#include <cuda_runtime.h>
#include <math.h>

#define SPLITK 16

// ---------------- device scratch (no allocations allowed) ----------------
__device__ float g_part[SPLITK * 64 * 6144];  // split-K partials (max N=6144)
__device__ float g_q[64 * 4096];              // rope'd + pre-scaled q
__device__ float g_k[64 * 1024];              // rope'd new k
__device__ float g_v[64 * 1024];              // new v
__device__ float g_attn[64 * 4096];           // attention output
__device__ float g_o[64 * 4096];              // after W_o

// ---------------- f32x2 packed helpers ----------------
__device__ __forceinline__ unsigned long long pack2(float x) {
    unsigned long long r;
    asm("mov.b64 %0, {%1, %1};" : "=l"(r) : "r"(__float_as_uint(x)));
    return r;
}
__device__ __forceinline__ void ffma2(unsigned long long& d, unsigned long long a,
                                      unsigned long long b) {
    asm("fma.rn.f32x2 %0, %1, %2, %0;" : "+l"(d) : "l"(a), "l"(b));
}

// ---------------- GEMM: part[s][64][N] += A[64,Kslice] @ W[Ntile,Kslice]^T --------
// amode: 0 = A1 (x), 1 = g_attn, 2 = concat(x | g_o) with switch at k=4096
// Block: 256 threads, tile M=64 x N=128, Kc=16. Thread microtile 8 rows x 4 cols.
__global__ __launch_bounds__(256) void gemm_part(
    const float* __restrict__ A1,
    const float* __restrict__ W0, const float* __restrict__ W1,
    const float* __restrict__ W2, int nb1, int nb2, int K, int partN, int amode) {
    __shared__ float xs[16 * 64];
    __shared__ float ws[16 * 128];

    const int tid = threadIdx.x;
    const int tx = tid & 31;
    const int ty = tid >> 5;
    const int n0 = blockIdx.x * 128;

    const float* Wb;
    int nrel;
    if (n0 < nb1)      { Wb = W0; nrel = n0; }
    else if (n0 < nb2) { Wb = W1; nrel = n0 - nb1; }
    else               { Wb = W2; nrel = n0 - nb2; }

    const int S = gridDim.y;
    const int Ks = K / S;
    const int kt0 = blockIdx.y * Ks;

    unsigned long long acc0[8], acc1[8];
#pragma unroll
    for (int r = 0; r < 8; r++) { acc0[r] = 0ULL; acc1[r] = 0ULL; }

    // loader indices
    const int am = tid >> 2;        // 0..63  (row)
    const int ak = (tid & 3) * 4;   // 0,4,8,12
    const int wn = tid >> 1;        // 0..127 (weight row within tile)
    const int wk = (tid & 1) * 8;   // 0 or 8

    for (int kt = kt0; kt < kt0 + Ks; kt += 16) {
        // ---- load A tile [64 x 16] (transposed into k-major) ----
        {
            const int kg = kt + ak;
            const float* Ar;
            if (amode == 0)      Ar = A1 + am * 4096 + kg;
            else if (amode == 1) Ar = g_attn + am * 4096 + kg;
            else                 Ar = (kg < 4096) ? (A1 + am * 4096 + kg)
                                                  : (g_o + am * 4096 + (kg - 4096));
            float4 av = *(const float4*)Ar;
            xs[(ak + 0) * 64 + am] = av.x;
            xs[(ak + 1) * 64 + am] = av.y;
            xs[(ak + 2) * 64 + am] = av.z;
            xs[(ak + 3) * 64 + am] = av.w;
        }
        // ---- load W tile [128 x 16] (transposed into k-major) ----
        {
            const float* Wrow = Wb + (size_t)(nrel + wn) * K + kt + wk;
            float4 w0 = *(const float4*)Wrow;
            float4 w1 = *(const float4*)(Wrow + 4);
            ws[(wk + 0) * 128 + wn] = w0.x;
            ws[(wk + 1) * 128 + wn] = w0.y;
            ws[(wk + 2) * 128 + wn] = w0.z;
            ws[(wk + 3) * 128 + wn] = w0.w;
            ws[(wk + 4) * 128 + wn] = w1.x;
            ws[(wk + 5) * 128 + wn] = w1.y;
            ws[(wk + 6) * 128 + wn] = w1.z;
            ws[(wk + 7) * 128 + wn] = w1.w;
        }
        __syncthreads();

        const unsigned long long* wsq = (const unsigned long long*)ws;
#pragma unroll
        for (int kk = 0; kk < 16; kk++) {
            const unsigned long long wA = wsq[kk * 64 + tx];
            const unsigned long long wB = wsq[kk * 64 + 32 + tx];
#pragma unroll
            for (int r = 0; r < 8; r++) {
                unsigned long long xx = pack2(xs[kk * 64 + ty * 8 + r]);
                ffma2(acc0[r], xx, wA);
                ffma2(acc1[r], xx, wB);
            }
        }
        __syncthreads();
    }

    // ---- write partials ----
    const int s = blockIdx.y;
#pragma unroll
    for (int r = 0; r < 8; r++) {
        const int row = ty * 8 + r;
        unsigned long long* p =
            (unsigned long long*)(g_part + (size_t)(s * 64 + row) * partN + n0);
        p[tx] = acc0[r];
        p[32 + tx] = acc1[r];
    }
}

// ---------------- pos (int32 / fp32 agnostic) ----------------
__device__ __forceinline__ float read_pos(const void* p) {
    int iv = *(const int*)p;
    if (iv >= 0 && iv < (1 << 26)) return (float)iv;
    return *(const float*)p;
}

// ---------------- reduce split-K partials of QKV + RoPE ----------------
// partN = 6144 : cols [0,4096) = q, [4096,5120) = k, [5120,6144) = v
__global__ __launch_bounds__(256) void reduce_rope_kernel(const void* posp) {
    const int p = blockIdx.x * 256 + threadIdx.x;  // pair index, 64*3072 total
    const int m = p / 3072;
    const int c = (p % 3072) * 2;

    float a0 = 0.f, a1 = 0.f;
#pragma unroll
    for (int s = 0; s < SPLITK; s++) {
        const size_t base = (size_t)(s * 64 + m) * 6144 + c;
        a0 += g_part[base];
        a1 += g_part[base + 1];
    }

    if (c < 5120) {
        const float pos = read_pos(posp);
        const float ex = (float)(c & 127) * (1.0f / 128.0f);
        const float inv = powf(10000.0f, -ex);
        const float ang = pos * inv;
        float sn, cs;
        sincosf(ang, &sn, &cs);
        const float r0 = a0 * cs - a1 * sn;
        const float r1 = a0 * sn + a1 * cs;
        if (c < 4096) {
            const float sc = 0.08838834764831845f;  // 1/sqrt(128), folded into q
            g_q[m * 4096 + c]     = r0 * sc;
            g_q[m * 4096 + c + 1] = r1 * sc;
        } else {
            g_k[m * 1024 + (c - 4096)]     = r0;
            g_k[m * 1024 + (c - 4096) + 1] = r1;
        }
    } else {
        g_v[m * 1024 + (c - 5120)]     = a0;
        g_v[m * 1024 + (c - 5120) + 1] = a1;
    }
}

// ---------------- attention: one block per (b, kv) ----------------
__global__ __launch_bounds__(256) void attn_kernel(const float* __restrict__ kcache,
                                                   const float* __restrict__ vcache) {
    __shared__ float sq[4 * 128];
    __shared__ float ss[4 * 2048];
    __shared__ float red[8];
    __shared__ float sginv[4];
    __shared__ float spv[4 * 128];

    const int tid = threadIdx.x;
    const int bk = blockIdx.x;       // b*8 + kv
    const int b = bk >> 3;
    const int kv = bk & 7;

    // load pre-scaled q for 4 groups
    for (int i = tid; i < 512; i += 256) sq[i] = g_q[b * 4096 + kv * 512 + i];
    __syncthreads();

    // ---- scores: warp per key ----
    const int wid = tid >> 5, lane = tid & 31;
    const float* kbase = kcache + (size_t)bk * (2048 * 128);
    const float4 q0 = *(const float4*)(sq + 0 * 128 + lane * 4);
    const float4 q1 = *(const float4*)(sq + 1 * 128 + lane * 4);
    const float4 q2 = *(const float4*)(sq + 2 * 128 + lane * 4);
    const float4 q3 = *(const float4*)(sq + 3 * 128 + lane * 4);

#pragma unroll 2
    for (int key = wid; key < 2048; key += 8) {
        float4 kk;
        if (key < 2047)
            kk = *(const float4*)(kbase + (size_t)(key + 1) * 128 + lane * 4);
        else
            kk = *(const float4*)(g_k + bk * 128 + lane * 4);
        float s0 = kk.x * q0.x + kk.y * q0.y + kk.z * q0.z + kk.w * q0.w;
        float s1 = kk.x * q1.x + kk.y * q1.y + kk.z * q1.z + kk.w * q1.w;
        float s2 = kk.x * q2.x + kk.y * q2.y + kk.z * q2.z + kk.w * q2.w;
        float s3 = kk.x * q3.x + kk.y * q3.y + kk.z * q3.z + kk.w * q3.w;
#pragma unroll
        for (int off = 16; off; off >>= 1) {
            s0 += __shfl_xor_sync(0xffffffffu, s0, off);
            s1 += __shfl_xor_sync(0xffffffffu, s1, off);
            s2 += __shfl_xor_sync(0xffffffffu, s2, off);
            s3 += __shfl_xor_sync(0xffffffffu, s3, off);
        }
        if (lane == 0) {
            ss[0 * 2048 + key] = s0;
            ss[1 * 2048 + key] = s1;
            ss[2 * 2048 + key] = s2;
            ss[3 * 2048 + key] = s3;
        }
    }
    __syncthreads();

    // ---- softmax: 64 threads (2 warps) per group ----
    const int gg = tid >> 6, t64 = tid & 63;
    float mx = -1e30f;
    for (int w = t64; w < 2048; w += 64) mx = fmaxf(mx, ss[gg * 2048 + w]);
#pragma unroll
    for (int off = 16; off; off >>= 1)
        mx = fmaxf(mx, __shfl_xor_sync(0xffffffffu, mx, off));
    if (lane == 0) red[wid] = mx;
    __syncthreads();
    mx = fmaxf(red[gg * 2], red[gg * 2 + 1]);

    float sm = 0.f;
    for (int w = t64; w < 2048; w += 64) {
        const float e = __expf(ss[gg * 2048 + w] - mx);
        ss[gg * 2048 + w] = e;
        sm += e;
    }
#pragma unroll
    for (int off = 16; off; off >>= 1) sm += __shfl_xor_sync(0xffffffffu, sm, off);
    __syncthreads();  // all reads of red (max phase) done
    if (lane == 0) red[wid] = sm;
    __syncthreads();
    if (tid < 4) sginv[tid] = 1.0f / (red[tid * 2] + red[tid * 2 + 1]);
    __syncthreads();

    // ---- PV: thread owns d, 2-way split over keys ----
    const int d = tid & 127, half = tid >> 7;
    const float* vbase = vcache + (size_t)bk * (2048 * 128);
    float a0 = 0.f, a1 = 0.f, a2 = 0.f, a3 = 0.f;
    const int wbeg = half * 1024;
#pragma unroll 4
    for (int w = wbeg; w < wbeg + 1024; w++) {
        const float v = (w < 2047) ? vbase[(size_t)(w + 1) * 128 + d]
                                   : g_v[bk * 128 + d];
        a0 += ss[0 * 2048 + w] * v;
        a1 += ss[1 * 2048 + w] * v;
        a2 += ss[2 * 2048 + w] * v;
        a3 += ss[3 * 2048 + w] * v;
    }
    if (half == 1) {
        spv[0 * 128 + d] = a0;
        spv[1 * 128 + d] = a1;
        spv[2 * 128 + d] = a2;
        spv[3 * 128 + d] = a3;
    }
    __syncthreads();
    if (half == 0) {
        float* ob = g_attn + b * 4096 + kv * 512;
        ob[0 * 128 + d] = (a0 + spv[0 * 128 + d]) * sginv[0];
        ob[1 * 128 + d] = (a1 + spv[1 * 128 + d]) * sginv[1];
        ob[2 * 128 + d] = (a2 + spv[2 * 128 + d]) * sginv[2];
        ob[3 * 128 + d] = (a3 + spv[3 * 128 + d]) * sginv[3];
    }
}

// ---------------- reduce split-K partials of W_o -> g_o ----------------
__global__ __launch_bounds__(256) void reduce_o_kernel() {
    const int i = blockIdx.x * 256 + threadIdx.x;  // 64*4096
    const int m = i >> 12, n = i & 4095;
    float z = 0.f;
#pragma unroll
    for (int s = 0; s < SPLITK; s++) z += g_part[(size_t)(s * 64 + m) * 4096 + n];
    g_o[i] = z;
}

// ---------------- reduce gate partials + sigmoid + final combine ----------------
__global__ __launch_bounds__(256) void final_kernel(const float* __restrict__ x,
                                                    const float* __restrict__ gb,
                                                    float* __restrict__ out) {
    const int i = blockIdx.x * 256 + threadIdx.x;  // 64*4096
    const int m = i >> 12, n = i & 4095;
    float z = 0.f;
#pragma unroll
    for (int s = 0; s < SPLITK; s++) z += g_part[(size_t)(s * 64 + m) * 4096 + n];
    z += gb[n];
    const float sig = 1.0f / (1.0f + __expf(-z));
    out[i] = x[i] + sig * g_o[i];
}

// ---------------- launch ----------------
extern "C" void kernel_launch(void* const* d_in, const int* in_sizes, int n_in,
                              void* d_out, int out_size) {
    const float* x  = (const float*)d_in[0];
    const float* kc = (const float*)d_in[1];
    const float* vc = (const float*)d_in[2];
    const float* Wq = (const float*)d_in[3];
    const float* Wk = (const float*)d_in[4];
    const float* Wv = (const float*)d_in[5];
    const float* Wo = (const float*)d_in[6];
    const float* gw = (const float*)d_in[7];
    const float* gb = (const float*)d_in[8];
    const void*  pp = d_in[9];
    float* out = (float*)d_out;

    const int BIG = 1 << 30;

    // 1. fused QKV projection (split-K x16, N = 6144)  -> 768 blocks
    gemm_part<<<dim3(48, SPLITK), 256>>>(x, Wq, Wk, Wv, 4096, 5120, 4096, 6144, 0);
    // 2. reduce + RoPE (+ fold 1/sqrt(dh) into q)
    reduce_rope_kernel<<<768, 256>>>(pp);
    // 3. attention over sliding-window cache
    attn_kernel<<<512, 256>>>(kc, vc);
    // 4. output projection (A = g_attn) -> 512 blocks
    gemm_part<<<dim3(32, SPLITK), 256>>>(x, Wo, Wo, Wo, BIG, BIG, 4096, 4096, 1);
    reduce_o_kernel<<<1024, 256>>>();
    // 5. gate GEMM over concat(x, o), K = 8192 -> 512 blocks
    gemm_part<<<dim3(32, SPLITK), 256>>>(x, gw, gw, gw, BIG, BIG, 8192, 4096, 2);
    // 6. reduce + bias + sigmoid + residual combine
    final_kernel<<<1024, 256>>>(x, gb, out);
}

// round 5
// speedup vs baseline: 1.2682x; 1.0694x over previous
#include <cuda_runtime.h>
#include <math.h>

#define SPLITK 16

// ---------------- device scratch (no allocations allowed) ----------------
__device__ float g_part[SPLITK * 64 * 6144];  // split-K partials (max N=6144)
__device__ float g_q[64 * 4096];              // rope'd + pre-scaled q
__device__ float g_k[64 * 1024];              // rope'd new k
__device__ float g_v[64 * 1024];              // new v
__device__ float g_attn[64 * 4096];           // attention output
__device__ float g_o[64 * 4096];              // after W_o

// ---------------- f32x2 packed helpers ----------------
__device__ __forceinline__ unsigned long long pack2(float x) {
    unsigned long long r;
    asm("mov.b64 %0, {%1, %1};" : "=l"(r) : "r"(__float_as_uint(x)));
    return r;
}
__device__ __forceinline__ void ffma2(unsigned long long& d, unsigned long long a,
                                      unsigned long long b) {
    asm("fma.rn.f32x2 %0, %1, %2, %0;" : "+l"(d) : "l"(a), "l"(b));
}

// ---------------- GEMM: part[s][64][N] += A[64,Kslice] @ W[Ntile,Kslice]^T --------
// amode: 0 = A1 (x), 1 = g_attn, 2 = concat(x | g_o) with switch at k=4096
// Block: 256 threads, tile M=64 x N=128, Kc=16. Thread microtile 8 rows x 4 cols.
__global__ __launch_bounds__(256) void gemm_part(
    const float* __restrict__ A1,
    const float* __restrict__ W0, const float* __restrict__ W1,
    const float* __restrict__ W2, int nb1, int nb2, int K, int partN, int amode) {
    __shared__ float xs[16 * 64];
    __shared__ float ws[16 * 128];

    const int tid = threadIdx.x;
    const int tx = tid & 31;
    const int ty = tid >> 5;
    const int n0 = blockIdx.x * 128;

    const float* Wb;
    int nrel;
    if (n0 < nb1)      { Wb = W0; nrel = n0; }
    else if (n0 < nb2) { Wb = W1; nrel = n0 - nb1; }
    else               { Wb = W2; nrel = n0 - nb2; }

    const int S = gridDim.y;
    const int Ks = K / S;
    const int kt0 = blockIdx.y * Ks;

    unsigned long long acc0[8], acc1[8];
#pragma unroll
    for (int r = 0; r < 8; r++) { acc0[r] = 0ULL; acc1[r] = 0ULL; }

    // loader indices
    const int am = tid >> 2;        // 0..63  (row)
    const int ak = (tid & 3) * 4;   // 0,4,8,12
    const int wn = tid >> 1;        // 0..127 (weight row within tile)
    const int wk = (tid & 1) * 8;   // 0 or 8

    for (int kt = kt0; kt < kt0 + Ks; kt += 16) {
        // ---- load A tile [64 x 16] (transposed into k-major) ----
        {
            const int kg = kt + ak;
            const float* Ar;
            if (amode == 0)      Ar = A1 + am * 4096 + kg;
            else if (amode == 1) Ar = g_attn + am * 4096 + kg;
            else                 Ar = (kg < 4096) ? (A1 + am * 4096 + kg)
                                                  : (g_o + am * 4096 + (kg - 4096));
            float4 av = *(const float4*)Ar;
            xs[(ak + 0) * 64 + am] = av.x;
            xs[(ak + 1) * 64 + am] = av.y;
            xs[(ak + 2) * 64 + am] = av.z;
            xs[(ak + 3) * 64 + am] = av.w;
        }
        // ---- load W tile [128 x 16] (transposed into k-major) ----
        {
            const float* Wrow = Wb + (size_t)(nrel + wn) * K + kt + wk;
            float4 w0 = *(const float4*)Wrow;
            float4 w1 = *(const float4*)(Wrow + 4);
            ws[(wk + 0) * 128 + wn] = w0.x;
            ws[(wk + 1) * 128 + wn] = w0.y;
            ws[(wk + 2) * 128 + wn] = w0.z;
            ws[(wk + 3) * 128 + wn] = w0.w;
            ws[(wk + 4) * 128 + wn] = w1.x;
            ws[(wk + 5) * 128 + wn] = w1.y;
            ws[(wk + 6) * 128 + wn] = w1.z;
            ws[(wk + 7) * 128 + wn] = w1.w;
        }
        __syncthreads();

        const unsigned long long* wsq = (const unsigned long long*)ws;
#pragma unroll
        for (int kk = 0; kk < 16; kk++) {
            const unsigned long long wA = wsq[kk * 64 + tx];
            const unsigned long long wB = wsq[kk * 64 + 32 + tx];
            // vectorized x loads: 2x LDS.128 (broadcast) instead of 8x LDS.32
            const float4 xa = *(const float4*)(xs + kk * 64 + ty * 8);
            const float4 xb = *(const float4*)(xs + kk * 64 + ty * 8 + 4);
            unsigned long long x;
            x = pack2(xa.x); ffma2(acc0[0], x, wA); ffma2(acc1[0], x, wB);
            x = pack2(xa.y); ffma2(acc0[1], x, wA); ffma2(acc1[1], x, wB);
            x = pack2(xa.z); ffma2(acc0[2], x, wA); ffma2(acc1[2], x, wB);
            x = pack2(xa.w); ffma2(acc0[3], x, wA); ffma2(acc1[3], x, wB);
            x = pack2(xb.x); ffma2(acc0[4], x, wA); ffma2(acc1[4], x, wB);
            x = pack2(xb.y); ffma2(acc0[5], x, wA); ffma2(acc1[5], x, wB);
            x = pack2(xb.z); ffma2(acc0[6], x, wA); ffma2(acc1[6], x, wB);
            x = pack2(xb.w); ffma2(acc0[7], x, wA); ffma2(acc1[7], x, wB);
        }
        __syncthreads();
    }

    // ---- write partials ----
    const int s = blockIdx.y;
#pragma unroll
    for (int r = 0; r < 8; r++) {
        const int row = ty * 8 + r;
        unsigned long long* p =
            (unsigned long long*)(g_part + (size_t)(s * 64 + row) * partN + n0);
        p[tx] = acc0[r];
        p[32 + tx] = acc1[r];
    }
}

// ---------------- pos (int32 / fp32 agnostic) ----------------
__device__ __forceinline__ float read_pos(const void* p) {
    int iv = *(const int*)p;
    if (iv >= 0 && iv < (1 << 26)) return (float)iv;
    return *(const float*)p;
}

// ---------------- reduce split-K partials of QKV + RoPE ----------------
// partN = 6144 : cols [0,4096) = q, [4096,5120) = k, [5120,6144) = v
__global__ __launch_bounds__(256) void reduce_rope_kernel(const void* posp) {
    const int p = blockIdx.x * 256 + threadIdx.x;  // pair index, 64*3072 total
    const int m = p / 3072;
    const int c = (p % 3072) * 2;

    float a0 = 0.f, a1 = 0.f;
#pragma unroll
    for (int s = 0; s < SPLITK; s++) {
        const size_t base = (size_t)(s * 64 + m) * 6144 + c;
        a0 += g_part[base];
        a1 += g_part[base + 1];
    }

    if (c < 5120) {
        const float pos = read_pos(posp);
        const float ex = (float)(c & 127) * (1.0f / 128.0f);
        const float inv = powf(10000.0f, -ex);
        const float ang = pos * inv;
        float sn, cs;
        sincosf(ang, &sn, &cs);
        const float r0 = a0 * cs - a1 * sn;
        const float r1 = a0 * sn + a1 * cs;
        if (c < 4096) {
            const float sc = 0.08838834764831845f;  // 1/sqrt(128), folded into q
            g_q[m * 4096 + c]     = r0 * sc;
            g_q[m * 4096 + c + 1] = r1 * sc;
        } else {
            g_k[m * 1024 + (c - 4096)]     = r0;
            g_k[m * 1024 + (c - 4096) + 1] = r1;
        }
    } else {
        g_v[m * 1024 + (c - 5120)]     = a0;
        g_v[m * 1024 + (c - 5120) + 1] = a1;
    }
}

// ---------------- attention: one block per (b, kv) ----------------
__global__ __launch_bounds__(256) void attn_kernel(const float* __restrict__ kcache,
                                                   const float* __restrict__ vcache) {
    __shared__ float sq[4 * 128];
    __shared__ float ss[4 * 2048];
    __shared__ float red[8];
    __shared__ float sginv[4];
    __shared__ float spv[8 * 4 * 128];

    const int tid = threadIdx.x;
    const int bk = blockIdx.x;       // b*8 + kv
    const int b = bk >> 3;
    const int kv = bk & 7;

    // load pre-scaled q for 4 groups
    for (int i = tid; i < 512; i += 256) sq[i] = g_q[b * 4096 + kv * 512 + i];
    __syncthreads();

    // ---- scores: warp per key ----
    const int wid = tid >> 5, lane = tid & 31;
    const float* kbase = kcache + (size_t)bk * (2048 * 128);
    const float4 q0 = *(const float4*)(sq + 0 * 128 + lane * 4);
    const float4 q1 = *(const float4*)(sq + 1 * 128 + lane * 4);
    const float4 q2 = *(const float4*)(sq + 2 * 128 + lane * 4);
    const float4 q3 = *(const float4*)(sq + 3 * 128 + lane * 4);

    const int octet = lane >> 3;         // 0..3 -> which group this octet reduces
    const bool octlead = (lane & 7) == 0;

#pragma unroll 2
    for (int key = wid; key < 2048; key += 8) {
        float4 kk;
        if (key < 2047)
            kk = *(const float4*)(kbase + (size_t)(key + 1) * 128 + lane * 4);
        else
            kk = *(const float4*)(g_k + bk * 128 + lane * 4);
        float s0 = kk.x * q0.x + kk.y * q0.y + kk.z * q0.z + kk.w * q0.w;
        float s1 = kk.x * q1.x + kk.y * q1.y + kk.z * q1.z + kk.w * q1.w;
        float s2 = kk.x * q2.x + kk.y * q2.y + kk.z * q2.z + kk.w * q2.w;
        float s3 = kk.x * q3.x + kk.y * q3.y + kk.z * q3.z + kk.w * q3.w;
        // partial butterfly over offsets 16, 8 for all four values (8 shfls)
#pragma unroll
        for (int off = 16; off >= 8; off >>= 1) {
            s0 += __shfl_xor_sync(0xffffffffu, s0, off);
            s1 += __shfl_xor_sync(0xffffffffu, s1, off);
            s2 += __shfl_xor_sync(0xffffffffu, s2, off);
            s3 += __shfl_xor_sync(0xffffffffu, s3, off);
        }
        // each 8-lane octet finishes one group's reduction (3 shfls)
        float z = (octet == 0) ? s0 : (octet == 1) ? s1 : (octet == 2) ? s2 : s3;
#pragma unroll
        for (int off = 4; off; off >>= 1) z += __shfl_xor_sync(0xffffffffu, z, off);
        if (octlead) ss[octet * 2048 + key] = z;
    }
    __syncthreads();

    // ---- softmax: 64 threads (2 warps) per group ----
    const int gg = tid >> 6, t64 = tid & 63;
    float mx = -1e30f;
    for (int w = t64; w < 2048; w += 64) mx = fmaxf(mx, ss[gg * 2048 + w]);
#pragma unroll
    for (int off = 16; off; off >>= 1)
        mx = fmaxf(mx, __shfl_xor_sync(0xffffffffu, mx, off));
    if (lane == 0) red[wid] = mx;
    __syncthreads();
    mx = fmaxf(red[gg * 2], red[gg * 2 + 1]);

    float sm = 0.f;
    for (int w = t64; w < 2048; w += 64) {
        const float e = __expf(ss[gg * 2048 + w] - mx);
        ss[gg * 2048 + w] = e;
        sm += e;
    }
#pragma unroll
    for (int off = 16; off; off >>= 1) sm += __shfl_xor_sync(0xffffffffu, sm, off);
    __syncthreads();  // all reads of red (max phase) done
    if (lane == 0) red[wid] = sm;
    __syncthreads();
    if (tid < 4) sginv[tid] = 1.0f / (red[tid * 2] + red[tid * 2 + 1]);
    __syncthreads();

    // ---- PV: thread owns 4 d-values (float4), 8-way key split ----
    const int d4 = (tid & 31) * 4;
    const int grp = tid >> 5;        // 0..7
    const float* vbase = vcache + (size_t)bk * (2048 * 128);
    float4 a0 = {0.f, 0.f, 0.f, 0.f}, a1 = a0, a2 = a0, a3 = a0;
    const int wbeg = grp * 256;
#pragma unroll 4
    for (int w = wbeg; w < wbeg + 256; w++) {
        const float* vp = (w < 2047) ? (vbase + (size_t)(w + 1) * 128 + d4)
                                     : (g_v + bk * 128 + d4);
        const float4 v = *(const float4*)vp;
        const float e0 = ss[0 * 2048 + w];
        const float e1 = ss[1 * 2048 + w];
        const float e2 = ss[2 * 2048 + w];
        const float e3 = ss[3 * 2048 + w];
        a0.x += e0 * v.x; a0.y += e0 * v.y; a0.z += e0 * v.z; a0.w += e0 * v.w;
        a1.x += e1 * v.x; a1.y += e1 * v.y; a1.z += e1 * v.z; a1.w += e1 * v.w;
        a2.x += e2 * v.x; a2.y += e2 * v.y; a2.z += e2 * v.z; a2.w += e2 * v.w;
        a3.x += e3 * v.x; a3.y += e3 * v.y; a3.z += e3 * v.z; a3.w += e3 * v.w;
    }
    *(float4*)(spv + (grp * 4 + 0) * 128 + d4) = a0;
    *(float4*)(spv + (grp * 4 + 1) * 128 + d4) = a1;
    *(float4*)(spv + (grp * 4 + 2) * 128 + d4) = a2;
    *(float4*)(spv + (grp * 4 + 3) * 128 + d4) = a3;
    __syncthreads();

    // final reduction over 8 key-groups: 512 outputs, 2 per thread
    for (int i = tid; i < 512; i += 256) {
        const int g = i >> 7, d = i & 127;
        float sum = 0.f;
#pragma unroll
        for (int p = 0; p < 8; p++) sum += spv[(p * 4 + g) * 128 + d];
        g_attn[b * 4096 + kv * 512 + g * 128 + d] = sum * sginv[g];
    }
}

// ---------------- reduce split-K partials of W_o -> g_o ----------------
__global__ __launch_bounds__(256) void reduce_o_kernel() {
    const int i = blockIdx.x * 256 + threadIdx.x;  // 64*4096
    const int m = i >> 12, n = i & 4095;
    float z = 0.f;
#pragma unroll
    for (int s = 0; s < SPLITK; s++) z += g_part[(size_t)(s * 64 + m) * 4096 + n];
    g_o[i] = z;
}

// ---------------- reduce gate partials + sigmoid + final combine ----------------
__global__ __launch_bounds__(256) void final_kernel(const float* __restrict__ x,
                                                    const float* __restrict__ gb,
                                                    float* __restrict__ out) {
    const int i = blockIdx.x * 256 + threadIdx.x;  // 64*4096
    const int m = i >> 12, n = i & 4095;
    float z = 0.f;
#pragma unroll
    for (int s = 0; s < SPLITK; s++) z += g_part[(size_t)(s * 64 + m) * 4096 + n];
    z += gb[n];
    const float sig = 1.0f / (1.0f + __expf(-z));
    out[i] = x[i] + sig * g_o[i];
}

// ---------------- launch ----------------
extern "C" void kernel_launch(void* const* d_in, const int* in_sizes, int n_in,
                              void* d_out, int out_size) {
    const float* x  = (const float*)d_in[0];
    const float* kc = (const float*)d_in[1];
    const float* vc = (const float*)d_in[2];
    const float* Wq = (const float*)d_in[3];
    const float* Wk = (const float*)d_in[4];
    const float* Wv = (const float*)d_in[5];
    const float* Wo = (const float*)d_in[6];
    const float* gw = (const float*)d_in[7];
    const float* gb = (const float*)d_in[8];
    const void*  pp = d_in[9];
    float* out = (float*)d_out;

    const int BIG = 1 << 30;

    // 1. fused QKV projection (split-K x16, N = 6144)  -> 768 blocks
    gemm_part<<<dim3(48, SPLITK), 256>>>(x, Wq, Wk, Wv, 4096, 5120, 4096, 6144, 0);
    // 2. reduce + RoPE (+ fold 1/sqrt(dh) into q)
    reduce_rope_kernel<<<768, 256>>>(pp);
    // 3. attention over sliding-window cache
    attn_kernel<<<512, 256>>>(kc, vc);
    // 4. output projection (A = g_attn) -> 512 blocks
    gemm_part<<<dim3(32, SPLITK), 256>>>(x, Wo, Wo, Wo, BIG, BIG, 4096, 4096, 1);
    reduce_o_kernel<<<1024, 256>>>();
    // 5. gate GEMM over concat(x, o), K = 8192 -> 512 blocks
    gemm_part<<<dim3(32, SPLITK), 256>>>(x, gw, gw, gw, BIG, BIG, 8192, 4096, 2);
    // 6. reduce + bias + sigmoid + residual combine
    final_kernel<<<1024, 256>>>(x, gb, out);
}

// round 8
// speedup vs baseline: 1.3565x; 1.0696x over previous
#include <cuda_runtime.h>
#include <math.h>

#define SPLITK 16

// ---------------- device scratch (no allocations allowed) ----------------
__device__ float g_part[SPLITK * 64 * 6144];  // split-K partials (max N=6144)
__device__ float g_q[64 * 4096];              // rope'd + pre-scaled q
__device__ float g_k[64 * 1024];              // rope'd new k
__device__ float g_v[64 * 1024];              // new v
__device__ float g_attn[64 * 4096];           // attention output
__device__ float g_o[64 * 4096];              // after W_o
__device__ float g_pv[2 * 512 * 4 * 128];     // flash-decode partial PV (unnormalized)
__device__ float g_m[2 * 512 * 4];            // per-half max
__device__ float g_s[2 * 512 * 4];            // per-half sum

// ---------------- f32x2 packed helpers ----------------
__device__ __forceinline__ unsigned long long pack2(float x) {
    unsigned long long r;
    asm("mov.b64 %0, {%1, %1};" : "=l"(r) : "r"(__float_as_uint(x)));
    return r;
}
__device__ __forceinline__ void ffma2(unsigned long long& d, unsigned long long a,
                                      unsigned long long b) {
    asm("fma.rn.f32x2 %0, %1, %2, %0;" : "+l"(d) : "l"(a), "l"(b));
}

// ---------------- GEMM: part[s][64][N] += A[64,Kslice] @ W[Ntile,Kslice]^T --------
// Double-buffered software pipeline: prefetch tile t+1 (LDG->regs) before
// computing tile t; STS into alternate buffer; ONE sync per tile.
// amode: 0 = A1 (x), 1 = g_attn, 2 = concat(x | g_o) with switch at k=4096
__global__ __launch_bounds__(256) void gemm_part(
    const float* __restrict__ A1,
    const float* __restrict__ W0, const float* __restrict__ W1,
    const float* __restrict__ W2, int nb1, int nb2, int K, int partN, int amode) {
    __shared__ float xs[2][16 * 64];
    __shared__ float ws[2][16 * 128];

    const int tid = threadIdx.x;
    const int tx = tid & 31;
    const int ty = tid >> 5;
    const int n0 = blockIdx.x * 128;

    const float* Wb;
    int nrel;
    if (n0 < nb1)      { Wb = W0; nrel = n0; }
    else if (n0 < nb2) { Wb = W1; nrel = n0 - nb1; }
    else               { Wb = W2; nrel = n0 - nb2; }

    const int S = gridDim.y;
    const int Ks = K / S;
    const int kt0 = blockIdx.y * Ks;
    const int ntiles = Ks / 16;

    unsigned long long acc0[8], acc1[8];
#pragma unroll
    for (int r = 0; r < 8; r++) { acc0[r] = 0ULL; acc1[r] = 0ULL; }

    // loader indices
    const int am = tid >> 2;        // 0..63  (A row)
    const int ak = (tid & 3) * 4;   // 0,4,8,12
    const int wn = tid >> 1;        // 0..127 (W row within tile)
    const int wk = (tid & 1) * 8;   // 0 or 8

    // per-thread base pointers
    const float* Abase1;
    const float* Abase2 = g_o + am * 4096 + ak - 4096;  // for amode 2, kg >= 4096
    if (amode == 1) Abase1 = g_attn + am * 4096 + ak;
    else            Abase1 = A1 + am * 4096 + ak;
    const float* Wbase = Wb + (size_t)(nrel + wn) * K + wk;

    float4 pa, pw0, pw1;
    // ---- prologue: load tile 0 ----
    {
        const int kg = kt0 + ak;
        const float* Ar = (amode == 2 && kg >= 4096) ? (Abase2 + kt0) : (Abase1 + kt0);
        pa = *(const float4*)Ar;
        const float* Wr = Wbase + kt0;
        pw0 = *(const float4*)Wr;
        pw1 = *(const float4*)(Wr + 4);
    }
    {
        xs[0][(ak + 0) * 64 + am] = pa.x;
        xs[0][(ak + 1) * 64 + am] = pa.y;
        xs[0][(ak + 2) * 64 + am] = pa.z;
        xs[0][(ak + 3) * 64 + am] = pa.w;
        ws[0][(wk + 0) * 128 + wn] = pw0.x;
        ws[0][(wk + 1) * 128 + wn] = pw0.y;
        ws[0][(wk + 2) * 128 + wn] = pw0.z;
        ws[0][(wk + 3) * 128 + wn] = pw0.w;
        ws[0][(wk + 4) * 128 + wn] = pw1.x;
        ws[0][(wk + 5) * 128 + wn] = pw1.y;
        ws[0][(wk + 6) * 128 + wn] = pw1.z;
        ws[0][(wk + 7) * 128 + wn] = pw1.w;
    }
    __syncthreads();

    for (int t = 0; t < ntiles; t++) {
        const int buf = t & 1;
        const bool more = (t + 1) < ntiles;
        // ---- prefetch tile t+1 into registers ----
        if (more) {
            const int kt = kt0 + (t + 1) * 16;
            const int kg = kt + ak;
            const float* Ar = (amode == 2 && kg >= 4096) ? (Abase2 + kt) : (Abase1 + kt);
            pa = *(const float4*)Ar;
            const float* Wr = Wbase + kt;
            pw0 = *(const float4*)Wr;
            pw1 = *(const float4*)(Wr + 4);
        }
        // ---- compute on buf ----
        const unsigned long long* wsq = (const unsigned long long*)ws[buf];
        const float* xsb = xs[buf];
#pragma unroll
        for (int kk = 0; kk < 16; kk++) {
            const unsigned long long wA = wsq[kk * 64 + tx];
            const unsigned long long wB = wsq[kk * 64 + 32 + tx];
            const float4 xa = *(const float4*)(xsb + kk * 64 + ty * 8);
            const float4 xb = *(const float4*)(xsb + kk * 64 + ty * 8 + 4);
            unsigned long long x;
            x = pack2(xa.x); ffma2(acc0[0], x, wA); ffma2(acc1[0], x, wB);
            x = pack2(xa.y); ffma2(acc0[1], x, wA); ffma2(acc1[1], x, wB);
            x = pack2(xa.z); ffma2(acc0[2], x, wA); ffma2(acc1[2], x, wB);
            x = pack2(xa.w); ffma2(acc0[3], x, wA); ffma2(acc1[3], x, wB);
            x = pack2(xb.x); ffma2(acc0[4], x, wA); ffma2(acc1[4], x, wB);
            x = pack2(xb.y); ffma2(acc0[5], x, wA); ffma2(acc1[5], x, wB);
            x = pack2(xb.z); ffma2(acc0[6], x, wA); ffma2(acc1[6], x, wB);
            x = pack2(xb.w); ffma2(acc0[7], x, wA); ffma2(acc1[7], x, wB);
        }
        // ---- STS tile t+1 into the other buffer ----
        if (more) {
            const int nb = buf ^ 1;
            xs[nb][(ak + 0) * 64 + am] = pa.x;
            xs[nb][(ak + 1) * 64 + am] = pa.y;
            xs[nb][(ak + 2) * 64 + am] = pa.z;
            xs[nb][(ak + 3) * 64 + am] = pa.w;
            ws[nb][(wk + 0) * 128 + wn] = pw0.x;
            ws[nb][(wk + 1) * 128 + wn] = pw0.y;
            ws[nb][(wk + 2) * 128 + wn] = pw0.z;
            ws[nb][(wk + 3) * 128 + wn] = pw0.w;
            ws[nb][(wk + 4) * 128 + wn] = pw1.x;
            ws[nb][(wk + 5) * 128 + wn] = pw1.y;
            ws[nb][(wk + 6) * 128 + wn] = pw1.z;
            ws[nb][(wk + 7) * 128 + wn] = pw1.w;
            __syncthreads();
        }
    }

    // ---- write partials ----
    const int s = blockIdx.y;
#pragma unroll
    for (int r = 0; r < 8; r++) {
        const int row = ty * 8 + r;
        unsigned long long* p =
            (unsigned long long*)(g_part + (size_t)(s * 64 + row) * partN + n0);
        p[tx] = acc0[r];
        p[32 + tx] = acc1[r];
    }
}

// ---------------- pos (int32 / fp32 agnostic) ----------------
__device__ __forceinline__ float read_pos(const void* p) {
    int iv = *(const int*)p;
    if (iv >= 0 && iv < (1 << 26)) return (float)iv;
    return *(const float*)p;
}

// ---------------- reduce split-K partials of QKV + RoPE ----------------
__global__ __launch_bounds__(256) void reduce_rope_kernel(const void* posp) {
    const int p = blockIdx.x * 256 + threadIdx.x;  // pair index, 64*3072 total
    const int m = p / 3072;
    const int c = (p % 3072) * 2;

    float a0 = 0.f, a1 = 0.f;
#pragma unroll
    for (int s = 0; s < SPLITK; s++) {
        const size_t base = (size_t)(s * 64 + m) * 6144 + c;
        a0 += g_part[base];
        a1 += g_part[base + 1];
    }

    if (c < 5120) {
        const float pos = read_pos(posp);
        const float ex = (float)(c & 127) * (1.0f / 128.0f);
        const float inv = powf(10000.0f, -ex);
        const float ang = pos * inv;
        float sn, cs;
        sincosf(ang, &sn, &cs);
        const float r0 = a0 * cs - a1 * sn;
        const float r1 = a0 * sn + a1 * cs;
        if (c < 4096) {
            const float sc = 0.08838834764831845f;  // 1/sqrt(128), folded into q
            g_q[m * 4096 + c]     = r0 * sc;
            g_q[m * 4096 + c + 1] = r1 * sc;
        } else {
            g_k[m * 1024 + (c - 4096)]     = r0;
            g_k[m * 1024 + (c - 4096) + 1] = r1;
        }
    } else {
        g_v[m * 1024 + (c - 5120)]     = a0;
        g_v[m * 1024 + (c - 5120) + 1] = a1;
    }
}

// ---------------- attention part: one block per (b, kv, half) ----------------
__global__ __launch_bounds__(256) void attn_part_kernel(const float* __restrict__ kcache,
                                                        const float* __restrict__ vcache) {
    __shared__ float sq[4 * 128];
    __shared__ float ss[4 * 1024];
    __shared__ float red[8];
    __shared__ float sms[4];
    __shared__ float spv[8 * 4 * 128];

    const int tid = threadIdx.x;
    const int blk = blockIdx.x;      // bk*2 + half
    const int bk = blk >> 1;
    const int half = blk & 1;
    const int b = bk >> 3;
    const int kv = bk & 7;
    const int kbeg = half * 1024;

    for (int i = tid; i < 512; i += 256) sq[i] = g_q[b * 4096 + kv * 512 + i];
    __syncthreads();

    // ---- scores: warp per key ----
    const int wid = tid >> 5, lane = tid & 31;
    const float* kbase = kcache + (size_t)bk * (2048 * 128);
    const float4 q0 = *(const float4*)(sq + 0 * 128 + lane * 4);
    const float4 q1 = *(const float4*)(sq + 1 * 128 + lane * 4);
    const float4 q2 = *(const float4*)(sq + 2 * 128 + lane * 4);
    const float4 q3 = *(const float4*)(sq + 3 * 128 + lane * 4);

    const int octet = lane >> 3;
    const bool octlead = (lane & 7) == 0;

#pragma unroll 2
    for (int key = kbeg + wid; key < kbeg + 1024; key += 8) {
        float4 kk;
        if (key < 2047)
            kk = *(const float4*)(kbase + (size_t)(key + 1) * 128 + lane * 4);
        else
            kk = *(const float4*)(g_k + bk * 128 + lane * 4);
        float s0 = kk.x * q0.x + kk.y * q0.y + kk.z * q0.z + kk.w * q0.w;
        float s1 = kk.x * q1.x + kk.y * q1.y + kk.z * q1.z + kk.w * q1.w;
        float s2 = kk.x * q2.x + kk.y * q2.y + kk.z * q2.z + kk.w * q2.w;
        float s3 = kk.x * q3.x + kk.y * q3.y + kk.z * q3.z + kk.w * q3.w;
#pragma unroll
        for (int off = 16; off >= 8; off >>= 1) {
            s0 += __shfl_xor_sync(0xffffffffu, s0, off);
            s1 += __shfl_xor_sync(0xffffffffu, s1, off);
            s2 += __shfl_xor_sync(0xffffffffu, s2, off);
            s3 += __shfl_xor_sync(0xffffffffu, s3, off);
        }
        float z = (octet == 0) ? s0 : (octet == 1) ? s1 : (octet == 2) ? s2 : s3;
#pragma unroll
        for (int off = 4; off; off >>= 1) z += __shfl_xor_sync(0xffffffffu, z, off);
        if (octlead) ss[octet * 1024 + (key - kbeg)] = z;
    }
    __syncthreads();

    // ---- partial softmax: 64 threads per group over 1024 keys ----
    const int gg = tid >> 6, t64 = tid & 63;
    float mx = -1e30f;
    for (int w = t64; w < 1024; w += 64) mx = fmaxf(mx, ss[gg * 1024 + w]);
#pragma unroll
    for (int off = 16; off; off >>= 1)
        mx = fmaxf(mx, __shfl_xor_sync(0xffffffffu, mx, off));
    if (lane == 0) red[wid] = mx;
    __syncthreads();
    mx = fmaxf(red[gg * 2], red[gg * 2 + 1]);

    float sm = 0.f;
    for (int w = t64; w < 1024; w += 64) {
        const float e = __expf(ss[gg * 1024 + w] - mx);
        ss[gg * 1024 + w] = e;
        sm += e;
    }
#pragma unroll
    for (int off = 16; off; off >>= 1) sm += __shfl_xor_sync(0xffffffffu, sm, off);
    __syncthreads();  // all reads of red (max phase) done
    if (lane == 0) red[wid] = sm;
    if (t64 == 0) sms[gg] = mx;   // FIX: export group-g max from a group-g thread
    __syncthreads();
    if (tid < 4) {
        g_m[half * 2048 + bk * 4 + tid] = sms[tid];
        g_s[half * 2048 + bk * 4 + tid] = red[tid * 2] + red[tid * 2 + 1];
    }

    // ---- PV: thread owns float4 of d, 8-way key split ----
    const int d4 = (tid & 31) * 4;
    const int grp = tid >> 5;
    const float* vbase = vcache + (size_t)bk * (2048 * 128);
    float4 a0 = {0.f, 0.f, 0.f, 0.f}, a1 = a0, a2 = a0, a3 = a0;
    const int wb = grp * 128;
#pragma unroll 4
    for (int w = wb; w < wb + 128; w++) {
        const int key = kbeg + w;
        const float* vp = (key < 2047) ? (vbase + (size_t)(key + 1) * 128 + d4)
                                       : (g_v + bk * 128 + d4);
        const float4 v = *(const float4*)vp;
        const float e0 = ss[0 * 1024 + w];
        const float e1 = ss[1 * 1024 + w];
        const float e2 = ss[2 * 1024 + w];
        const float e3 = ss[3 * 1024 + w];
        a0.x += e0 * v.x; a0.y += e0 * v.y; a0.z += e0 * v.z; a0.w += e0 * v.w;
        a1.x += e1 * v.x; a1.y += e1 * v.y; a1.z += e1 * v.z; a1.w += e1 * v.w;
        a2.x += e2 * v.x; a2.y += e2 * v.y; a2.z += e2 * v.z; a2.w += e2 * v.w;
        a3.x += e3 * v.x; a3.y += e3 * v.y; a3.z += e3 * v.z; a3.w += e3 * v.w;
    }
    *(float4*)(spv + (grp * 4 + 0) * 128 + d4) = a0;
    *(float4*)(spv + (grp * 4 + 1) * 128 + d4) = a1;
    *(float4*)(spv + (grp * 4 + 2) * 128 + d4) = a2;
    *(float4*)(spv + (grp * 4 + 3) * 128 + d4) = a3;
    __syncthreads();

    // reduce over 8 key-subgroups, write unnormalized partial
    for (int i = tid; i < 512; i += 256) {
        const int g = i >> 7, d = i & 127;
        float sum = 0.f;
#pragma unroll
        for (int p = 0; p < 8; p++) sum += spv[(p * 4 + g) * 128 + d];
        g_pv[((size_t)half * 512 + bk) * 512 + g * 128 + d] = sum;
    }
}

// ---------------- combine flash-decode halves -> g_attn ----------------
__global__ __launch_bounds__(256) void attn_combine_kernel() {
    const int i = blockIdx.x * 256 + threadIdx.x;  // 64*4096
    const int b = i >> 12;
    const int r = i & 4095;
    const int kv = r >> 9;
    const int g = (r >> 7) & 3;
    const int bk = b * 8 + kv;
    const int gi = bk * 4 + g;

    const float m0 = g_m[gi], m1 = g_m[2048 + gi];
    const float s0 = g_s[gi], s1 = g_s[2048 + gi];
    const float M = fmaxf(m0, m1);
    const float w0 = __expf(m0 - M), w1 = __expf(m1 - M);
    const float p0 = g_pv[(size_t)bk * 512 + (r & 511)];
    const float p1 = g_pv[(size_t)(512 + bk) * 512 + (r & 511)];
    g_attn[i] = (p0 * w0 + p1 * w1) / (s0 * w0 + s1 * w1);
}

// ---------------- reduce split-K partials of W_o -> g_o ----------------
__global__ __launch_bounds__(256) void reduce_o_kernel() {
    const int i = blockIdx.x * 256 + threadIdx.x;  // 64*4096
    const int m = i >> 12, n = i & 4095;
    float z = 0.f;
#pragma unroll
    for (int s = 0; s < SPLITK; s++) z += g_part[(size_t)(s * 64 + m) * 4096 + n];
    g_o[i] = z;
}

// ---------------- reduce gate partials + sigmoid + final combine ----------------
__global__ __launch_bounds__(256) void final_kernel(const float* __restrict__ x,
                                                    const float* __restrict__ gb,
                                                    float* __restrict__ out) {
    const int i = blockIdx.x * 256 + threadIdx.x;  // 64*4096
    const int m = i >> 12, n = i & 4095;
    float z = 0.f;
#pragma unroll
    for (int s = 0; s < SPLITK; s++) z += g_part[(size_t)(s * 64 + m) * 4096 + n];
    z += gb[n];
    const float sig = 1.0f / (1.0f + __expf(-z));
    out[i] = x[i] + sig * g_o[i];
}

// ---------------- launch ----------------
extern "C" void kernel_launch(void* const* d_in, const int* in_sizes, int n_in,
                              void* d_out, int out_size) {
    const float* x  = (const float*)d_in[0];
    const float* kc = (const float*)d_in[1];
    const float* vc = (const float*)d_in[2];
    const float* Wq = (const float*)d_in[3];
    const float* Wk = (const float*)d_in[4];
    const float* Wv = (const float*)d_in[5];
    const float* Wo = (const float*)d_in[6];
    const float* gw = (const float*)d_in[7];
    const float* gb = (const float*)d_in[8];
    const void*  pp = d_in[9];
    float* out = (float*)d_out;

    const int BIG = 1 << 30;

    // 1. fused QKV projection (split-K x16, N = 6144)
    gemm_part<<<dim3(48, SPLITK), 256>>>(x, Wq, Wk, Wv, 4096, 5120, 4096, 6144, 0);
    // 2. reduce + RoPE
    reduce_rope_kernel<<<768, 256>>>(pp);
    // 3. attention (flash-decode, 2 halves) + combine
    attn_part_kernel<<<1024, 256>>>(kc, vc);
    attn_combine_kernel<<<1024, 256>>>();
    // 4. output projection
    gemm_part<<<dim3(32, SPLITK), 256>>>(x, Wo, Wo, Wo, BIG, BIG, 4096, 4096, 1);
    reduce_o_kernel<<<1024, 256>>>();
    // 5. gate GEMM over concat(x, o), K = 8192
    gemm_part<<<dim3(32, SPLITK), 256>>>(x, gw, gw, gw, BIG, BIG, 8192, 4096, 2);
    // 6. reduce + bias + sigmoid + residual combine
    final_kernel<<<1024, 256>>>(x, gb, out);
}

// round 15
// speedup vs baseline: 1.7144x; 1.2639x over previous
#include <cuda_runtime.h>
#include <cuda_bf16.h>
#include <math.h>
#include <stdint.h>

// ---------------- device scratch (no allocations allowed) ----------------
__device__ float g_part[16 * 64 * 6144];      // split-K partials (max S=16, N=6144)
__device__ float g_q[64 * 4096];              // rope'd + pre-scaled q
__device__ float g_k[64 * 1024];              // rope'd new k
__device__ float g_v[64 * 1024];              // new v
__device__ float g_attn[64 * 4096];           // attention output
__device__ float g_o[64 * 4096];              // after W_o
__device__ float g_pv[2 * 512 * 4 * 128];     // flash-decode partial PV
__device__ float g_m[2 * 512 * 4];            // per-half max
__device__ float g_s[2 * 512 * 4];            // per-half sum

// ================= warp-mma helpers (baseline sm_80+ PTX, legal on sm_103) ====
__device__ __forceinline__ uint32_t s2u(const void* p) {
    uint32_t a;
    asm("{ .reg .u64 t; cvta.to.shared.u64 t, %1; cvt.u32.u64 %0, t; }"
        : "=r"(a) : "l"(p));
    return a;
}
__device__ __forceinline__ void ldm4(uint32_t* r, uint32_t addr) {
    asm volatile("ldmatrix.sync.aligned.m8n8.x4.shared.b16 {%0,%1,%2,%3}, [%4];"
                 : "=r"(r[0]), "=r"(r[1]), "=r"(r[2]), "=r"(r[3]) : "r"(addr));
}
__device__ __forceinline__ void mma16816(float* d, const uint32_t* a,
                                         uint32_t b0, uint32_t b1) {
    asm volatile(
        "mma.sync.aligned.m16n8k16.row.col.f32.bf16.bf16.f32 "
        "{%0,%1,%2,%3}, {%4,%5,%6,%7}, {%8,%9}, {%0,%1,%2,%3};"
        : "+f"(d[0]), "+f"(d[1]), "+f"(d[2]), "+f"(d[3])
        : "r"(a[0]), "r"(a[1]), "r"(a[2]), "r"(a[3]), "r"(b0), "r"(b1));
}
__device__ __forceinline__ uint32_t pkbf(__nv_bfloat16 a, __nv_bfloat16 b) {
    return (uint32_t)__bfloat16_as_ushort(a) |
           ((uint32_t)__bfloat16_as_ushort(b) << 16);
}

// smem geometry: rows padded to 40 bf16 (80B) for conflict-free ldmatrix
#define ROWB 80
#define OFF_AL 5120            // Ah: 64*80 = 5120B
#define OFF_WH 10240
#define OFF_WL 20480           // Wh: 128*80 = 10240B
#define BUFSZ 30720
#define SMEM_SZ (2 * BUFSZ)    // 61440 bytes, double-buffered

// hi/lo split + swizzle-free padded store of one float4 (4 bf16 hi + 4 bf16 lo)
__device__ __forceinline__ void cvt_sts(char* base, int hioff, int looff,
                                        int row, int c4, float4 v) {
    __nv_bfloat16 h0 = __float2bfloat16(v.x), h1 = __float2bfloat16(v.y);
    __nv_bfloat16 h2 = __float2bfloat16(v.z), h3 = __float2bfloat16(v.w);
    __nv_bfloat16 l0 = __float2bfloat16(v.x - __bfloat162float(h0));
    __nv_bfloat16 l1 = __float2bfloat16(v.y - __bfloat162float(h1));
    __nv_bfloat16 l2 = __float2bfloat16(v.z - __bfloat162float(h2));
    __nv_bfloat16 l3 = __float2bfloat16(v.w - __bfloat162float(h3));
    const int off = row * ROWB + c4 * 8;
    *(uint2*)(base + hioff + off) = make_uint2(pkbf(h0, h1), pkbf(h2, h3));
    *(uint2*)(base + looff + off) = make_uint2(pkbf(l0, l1), pkbf(l2, l3));
}

// ======= tensor-core GEMM: part[s][64][N] += A[64,Ks] @ W[N,Ks]^T =======
// amode: 0 = A1 (x), 1 = g_attn, 2 = concat(x | g_o), split at k=4096
// bf16 hi/lo 3-term split precision; block M=64 x N=128, K-slice 32, dbl-buffered.
__global__ __launch_bounds__(256) void gemm_mma(
    const float* __restrict__ A1,
    const float* __restrict__ W0, const float* __restrict__ W1,
    const float* __restrict__ W2,
    int nb1, int nb2, int K, int partN, int amode) {
    extern __shared__ __align__(16) char smem[];
    const uint32_t sb = s2u(smem);
    const int tid = threadIdx.x;
    const int wid = tid >> 5;
    const int lane = tid & 31;
    const int n0 = blockIdx.x * 128;

    const float* Wb;
    int nrel;
    if (n0 < nb1)      { Wb = W0; nrel = n0; }
    else if (n0 < nb2) { Wb = W1; nrel = n0 - nb1; }
    else               { Wb = W2; nrel = n0 - nb2; }

    const int S = gridDim.y;
    const int Ks = K / S;
    const int kt0 = blockIdx.y * Ks;
    const int nslices = Ks / 32;

    const int warpM = wid >> 2;  // 0..1
    const int warpN = wid & 3;   // 0..3

    float acc[2][4][4];
#pragma unroll
    for (int i = 0; i < 2; i++)
#pragma unroll
        for (int j = 0; j < 4; j++)
#pragma unroll
            for (int c = 0; c < 4; c++) acc[i][j][c] = 0.f;

    // loader indices: A rows ar0, ar0+32, cols c4*4; W rows wr0+32j
    const int ar0 = tid >> 3;        // 0..31
    const int c4 = tid & 7;          // 0..7 (float4 slot within 32-col slice)
    const float* Abase = (amode == 1) ? g_attn : A1;
    const float* Wrow0 = Wb + (size_t)(nrel + ar0) * K + c4 * 4;  // rows 0..31 (+32j)

    float4 pa[2], pw[4];
    // slice loaders
    auto loadA = [&](int kt) {
        const int kg = kt + c4 * 4;
        if (amode == 2 && kg >= 4096) {
            pa[0] = *(const float4*)(g_o + ar0 * 4096 + (kg - 4096));
            pa[1] = *(const float4*)(g_o + (ar0 + 32) * 4096 + (kg - 4096));
        } else {
            pa[0] = *(const float4*)(Abase + ar0 * 4096 + kg);
            pa[1] = *(const float4*)(Abase + (ar0 + 32) * 4096 + kg);
        }
    };
    auto loadW = [&](int kt) {
#pragma unroll
        for (int j = 0; j < 4; j++)
            pw[j] = *(const float4*)(Wrow0 + (size_t)j * 32 * K + kt);
    };
    auto stsAll = [&](int b) {
        char* base = smem + b * BUFSZ;
        cvt_sts(base, 0, OFF_AL, ar0, c4, pa[0]);
        cvt_sts(base, 0, OFF_AL, ar0 + 32, c4, pa[1]);
#pragma unroll
        for (int j = 0; j < 4; j++)
            cvt_sts(base, OFF_WH, OFF_WL, ar0 + 32 * j, c4, pw[j]);
    };

    const int lrow = lane & 7;
    const int msel = lane >> 3;
    // precomputed ldmatrix lane offsets (bytes within each operand section)
    const uint32_t aoff = (uint32_t)((warpM * 32 + lrow + ((msel & 1) << 3)) * ROWB +
                                     (((msel >> 1) << 3) * 2));
    const uint32_t boff = (uint32_t)((warpN * 32 + lrow + ((msel >> 1) << 3)) * ROWB +
                                     (((msel & 1) << 3) * 2));

    // ---- prologue ----
    loadA(kt0); loadW(kt0);
    stsAll(0);
    __syncthreads();

    for (int t = 0; t < nslices; t++) {
        const int buf = t & 1;
        if (t + 1 < nslices) { loadA(kt0 + (t + 1) * 32); loadW(kt0 + (t + 1) * 32); }

        const uint32_t sAh = sb + buf * BUFSZ;
        const uint32_t sAl = sAh + OFF_AL;
        const uint32_t sWh = sAh + OFF_WH;
        const uint32_t sWl = sAh + OFF_WL;
#pragma unroll
        for (int kb = 0; kb < 2; kb++) {   // two k16 chunks per slice
            const uint32_t kboff = (uint32_t)(kb * 32);  // 16 elems * 2B
            uint32_t ah[2][4], al[2][4], bh[2][4], bl[2][4];
#pragma unroll
            for (int mt = 0; mt < 2; mt++) {
                const uint32_t o = aoff + (uint32_t)(mt * 16 * ROWB) + kboff;
                ldm4(ah[mt], sAh + o);
                ldm4(al[mt], sAl + o);
            }
#pragma unroll
            for (int p = 0; p < 2; p++) {
                const uint32_t o = boff + (uint32_t)(p * 16 * ROWB) + kboff;
                ldm4(bh[p], sWh + o);
                ldm4(bl[p], sWl + o);
            }
#pragma unroll
            for (int mt = 0; mt < 2; mt++)
#pragma unroll
                for (int nt = 0; nt < 4; nt++) {
                    const int p = nt >> 1, h = (nt & 1) * 2;
                    mma16816(acc[mt][nt], ah[mt], bh[p][h], bh[p][h + 1]);
                    mma16816(acc[mt][nt], ah[mt], bl[p][h], bl[p][h + 1]);
                    mma16816(acc[mt][nt], al[mt], bh[p][h], bh[p][h + 1]);
                }
        }
        if (t + 1 < nslices) {
            __syncthreads();   // everyone done reading buf^1 from prev iter? (buf^1 = next)
            stsAll(buf ^ 1);
            __syncthreads();
        }
    }

    // ---- epilogue: write partials ----
    const int s = blockIdx.y;
#pragma unroll
    for (int mt = 0; mt < 2; mt++) {
        const int r0 = warpM * 32 + mt * 16 + (lane >> 2);
#pragma unroll
        for (int nt = 0; nt < 4; nt++) {
            const int c0 = n0 + warpN * 32 + nt * 8 + (lane & 3) * 2;
            float* p = g_part + (size_t)(s * 64 + r0) * partN + c0;
            p[0] = acc[mt][nt][0];
            p[1] = acc[mt][nt][1];
            float* p2 = p + 8 * partN;
            p2[0] = acc[mt][nt][2];
            p2[1] = acc[mt][nt][3];
        }
    }
}

// ---------------- pos (int32 / fp32 agnostic) ----------------
__device__ __forceinline__ float read_pos(const void* p) {
    int iv = *(const int*)p;
    if (iv >= 0 && iv < (1 << 26)) return (float)iv;
    return *(const float*)p;
}

// ---------------- reduce split-K partials of QKV + RoPE ----------------
__global__ __launch_bounds__(256) void reduce_rope_kernel(const void* posp, int S) {
    const int p = blockIdx.x * 256 + threadIdx.x;  // pair index, 64*3072 total
    const int m = p / 3072;
    const int c = (p % 3072) * 2;

    float a0 = 0.f, a1 = 0.f;
#pragma unroll 8
    for (int s = 0; s < S; s++) {
        const size_t base = (size_t)(s * 64 + m) * 6144 + c;
        a0 += g_part[base];
        a1 += g_part[base + 1];
    }

    if (c < 5120) {
        const float pos = read_pos(posp);
        const float ex = (float)(c & 127) * (1.0f / 128.0f);
        const float inv = powf(10000.0f, -ex);
        const float ang = pos * inv;
        float sn, cs;
        sincosf(ang, &sn, &cs);
        const float r0 = a0 * cs - a1 * sn;
        const float r1 = a0 * sn + a1 * cs;
        if (c < 4096) {
            const float sc = 0.08838834764831845f;  // 1/sqrt(128), folded into q
            g_q[m * 4096 + c]     = r0 * sc;
            g_q[m * 4096 + c + 1] = r1 * sc;
        } else {
            g_k[m * 1024 + (c - 4096)]     = r0;
            g_k[m * 1024 + (c - 4096) + 1] = r1;
        }
    } else {
        g_v[m * 1024 + (c - 5120)]     = a0;
        g_v[m * 1024 + (c - 5120) + 1] = a1;
    }
}

// ---------------- attention part: one block per (b, kv, half) ----------------
__global__ __launch_bounds__(256) void attn_part_kernel(const float* __restrict__ kcache,
                                                        const float* __restrict__ vcache) {
    __shared__ float sq[4 * 128];
    __shared__ float ss[4 * 1024];
    __shared__ float red[8];
    __shared__ float sms[4];
    __shared__ float spv[8 * 4 * 128];

    const int tid = threadIdx.x;
    const int blk = blockIdx.x;      // bk*2 + half
    const int bk = blk >> 1;
    const int half = blk & 1;
    const int b = bk >> 3;
    const int kv = bk & 7;
    const int kbeg = half * 1024;

    for (int i = tid; i < 512; i += 256) sq[i] = g_q[b * 4096 + kv * 512 + i];
    __syncthreads();

    // ---- scores: warp per key ----
    const int wid = tid >> 5, lane = tid & 31;
    const float* kbase = kcache + (size_t)bk * (2048 * 128);
    const float4 q0 = *(const float4*)(sq + 0 * 128 + lane * 4);
    const float4 q1 = *(const float4*)(sq + 1 * 128 + lane * 4);
    const float4 q2 = *(const float4*)(sq + 2 * 128 + lane * 4);
    const float4 q3 = *(const float4*)(sq + 3 * 128 + lane * 4);

    const int octet = lane >> 3;
    const bool octlead = (lane & 7) == 0;

#pragma unroll 2
    for (int key = kbeg + wid; key < kbeg + 1024; key += 8) {
        float4 kk;
        if (key < 2047)
            kk = *(const float4*)(kbase + (size_t)(key + 1) * 128 + lane * 4);
        else
            kk = *(const float4*)(g_k + bk * 128 + lane * 4);
        float s0 = kk.x * q0.x + kk.y * q0.y + kk.z * q0.z + kk.w * q0.w;
        float s1 = kk.x * q1.x + kk.y * q1.y + kk.z * q1.z + kk.w * q1.w;
        float s2 = kk.x * q2.x + kk.y * q2.y + kk.z * q2.z + kk.w * q2.w;
        float s3 = kk.x * q3.x + kk.y * q3.y + kk.z * q3.z + kk.w * q3.w;
#pragma unroll
        for (int off = 16; off >= 8; off >>= 1) {
            s0 += __shfl_xor_sync(0xffffffffu, s0, off);
            s1 += __shfl_xor_sync(0xffffffffu, s1, off);
            s2 += __shfl_xor_sync(0xffffffffu, s2, off);
            s3 += __shfl_xor_sync(0xffffffffu, s3, off);
        }
        float z = (octet == 0) ? s0 : (octet == 1) ? s1 : (octet == 2) ? s2 : s3;
#pragma unroll
        for (int off = 4; off; off >>= 1) z += __shfl_xor_sync(0xffffffffu, z, off);
        if (octlead) ss[octet * 1024 + (key - kbeg)] = z;
    }
    __syncthreads();

    // ---- partial softmax: 64 threads per group over 1024 keys ----
    const int gg = tid >> 6, t64 = tid & 63;
    float mx = -1e30f;
    for (int w = t64; w < 1024; w += 64) mx = fmaxf(mx, ss[gg * 1024 + w]);
#pragma unroll
    for (int off = 16; off; off >>= 1)
        mx = fmaxf(mx, __shfl_xor_sync(0xffffffffu, mx, off));
    if (lane == 0) red[wid] = mx;
    __syncthreads();
    mx = fmaxf(red[gg * 2], red[gg * 2 + 1]);

    float sm = 0.f;
    for (int w = t64; w < 1024; w += 64) {
        const float e = __expf(ss[gg * 1024 + w] - mx);
        ss[gg * 1024 + w] = e;
        sm += e;
    }
#pragma unroll
    for (int off = 16; off; off >>= 1) sm += __shfl_xor_sync(0xffffffffu, sm, off);
    __syncthreads();  // all reads of red (max phase) done
    if (lane == 0) red[wid] = sm;
    if (t64 == 0) sms[gg] = mx;   // group-g max exported by a group-g thread
    __syncthreads();
    if (tid < 4) {
        g_m[half * 2048 + bk * 4 + tid] = sms[tid];
        g_s[half * 2048 + bk * 4 + tid] = red[tid * 2] + red[tid * 2 + 1];
    }

    // ---- PV: thread owns float4 of d, 8-way key split ----
    const int d4 = (tid & 31) * 4;
    const int grp = tid >> 5;
    const float* vbase = vcache + (size_t)bk * (2048 * 128);
    float4 a0 = {0.f, 0.f, 0.f, 0.f}, a1 = a0, a2 = a0, a3 = a0;
    const int wb = grp * 128;
#pragma unroll 4
    for (int w = wb; w < wb + 128; w++) {
        const int key = kbeg + w;
        const float* vp = (key < 2047) ? (vbase + (size_t)(key + 1) * 128 + d4)
                                       : (g_v + bk * 128 + d4);
        const float4 v = *(const float4*)vp;
        const float e0 = ss[0 * 1024 + w];
        const float e1 = ss[1 * 1024 + w];
        const float e2 = ss[2 * 1024 + w];
        const float e3 = ss[3 * 1024 + w];
        a0.x += e0 * v.x; a0.y += e0 * v.y; a0.z += e0 * v.z; a0.w += e0 * v.w;
        a1.x += e1 * v.x; a1.y += e1 * v.y; a1.z += e1 * v.z; a1.w += e1 * v.w;
        a2.x += e2 * v.x; a2.y += e2 * v.y; a2.z += e2 * v.z; a2.w += e2 * v.w;
        a3.x += e3 * v.x; a3.y += e3 * v.y; a3.z += e3 * v.z; a3.w += e3 * v.w;
    }
    *(float4*)(spv + (grp * 4 + 0) * 128 + d4) = a0;
    *(float4*)(spv + (grp * 4 + 1) * 128 + d4) = a1;
    *(float4*)(spv + (grp * 4 + 2) * 128 + d4) = a2;
    *(float4*)(spv + (grp * 4 + 3) * 128 + d4) = a3;
    __syncthreads();

    // reduce over 8 key-subgroups, write unnormalized partial
    for (int i = tid; i < 512; i += 256) {
        const int g = i >> 7, d = i & 127;
        float sum = 0.f;
#pragma unroll
        for (int p = 0; p < 8; p++) sum += spv[(p * 4 + g) * 128 + d];
        g_pv[((size_t)half * 512 + bk) * 512 + g * 128 + d] = sum;
    }
}

// ---------------- combine flash-decode halves -> g_attn ----------------
__global__ __launch_bounds__(256) void attn_combine_kernel() {
    const int i = blockIdx.x * 256 + threadIdx.x;  // 64*4096
    const int b = i >> 12;
    const int r = i & 4095;
    const int kv = r >> 9;
    const int g = (r >> 7) & 3;
    const int bk = b * 8 + kv;
    const int gi = bk * 4 + g;

    const float m0 = g_m[gi], m1 = g_m[2048 + gi];
    const float s0 = g_s[gi], s1 = g_s[2048 + gi];
    const float M = fmaxf(m0, m1);
    const float w0 = __expf(m0 - M), w1 = __expf(m1 - M);
    const float p0 = g_pv[(size_t)bk * 512 + (r & 511)];
    const float p1 = g_pv[(size_t)(512 + bk) * 512 + (r & 511)];
    g_attn[i] = (p0 * w0 + p1 * w1) / (s0 * w0 + s1 * w1);
}

// ---------------- reduce split-K partials of W_o -> g_o ----------------
__global__ __launch_bounds__(256) void reduce_o_kernel(int S) {
    const int i = blockIdx.x * 256 + threadIdx.x;  // 64*4096
    const int m = i >> 12, n = i & 4095;
    float z = 0.f;
#pragma unroll 8
    for (int s = 0; s < S; s++) z += g_part[(size_t)(s * 64 + m) * 4096 + n];
    g_o[i] = z;
}

// ---------------- reduce gate partials + sigmoid + final combine ----------------
__global__ __launch_bounds__(256) void final_kernel(const float* __restrict__ x,
                                                    const float* __restrict__ gb,
                                                    float* __restrict__ out, int S) {
    const int i = blockIdx.x * 256 + threadIdx.x;  // 64*4096
    const int m = i >> 12, n = i & 4095;
    float z = 0.f;
#pragma unroll 8
    for (int s = 0; s < S; s++) z += g_part[(size_t)(s * 64 + m) * 4096 + n];
    z += gb[n];
    const float sig = 1.0f / (1.0f + __expf(-z));
    out[i] = x[i] + sig * g_o[i];
}

// ---------------- launch ----------------
extern "C" void kernel_launch(void* const* d_in, const int* in_sizes, int n_in,
                              void* d_out, int out_size) {
    const float* x  = (const float*)d_in[0];
    const float* kc = (const float*)d_in[1];
    const float* vc = (const float*)d_in[2];
    const float* Wq = (const float*)d_in[3];
    const float* Wk = (const float*)d_in[4];
    const float* Wv = (const float*)d_in[5];
    const float* Wo = (const float*)d_in[6];
    const float* gw = (const float*)d_in[7];
    const float* gb = (const float*)d_in[8];
    const void*  pp = d_in[9];
    float* out = (float*)d_out;

    const int BIG = 1 << 30;

    static int smem_set = 0;
    if (!smem_set) {
        cudaFuncSetAttribute((const void*)gemm_mma,
                             cudaFuncAttributeMaxDynamicSharedMemorySize, SMEM_SZ);
        smem_set = 1;
    }

    // 1. fused QKV projection (mma.sync bf16 split, split-K x8, N = 6144)
    gemm_mma<<<dim3(48, 8), 256, SMEM_SZ>>>(x, Wq, Wk, Wv, 4096, 5120, 4096, 6144, 0);
    // 2. reduce + RoPE
    reduce_rope_kernel<<<768, 256>>>(pp, 8);
    // 3. attention (flash-decode, 2 halves) + combine
    attn_part_kernel<<<1024, 256>>>(kc, vc);
    attn_combine_kernel<<<1024, 256>>>();
    // 4. output projection (split-K x8)
    gemm_mma<<<dim3(32, 8), 256, SMEM_SZ>>>(x, Wo, Wo, Wo, BIG, BIG, 4096, 4096, 1);
    reduce_o_kernel<<<1024, 256>>>(8);
    // 5. gate GEMM over concat(x, o), K = 8192 (split-K x16)
    gemm_mma<<<dim3(32, 16), 256, SMEM_SZ>>>(x, gw, gw, gw, BIG, BIG, 8192, 4096, 2);
    // 6. reduce + bias + sigmoid + residual combine
    final_kernel<<<1024, 256>>>(x, gb, out, 16);
}